// round 10
// baseline (speedup 1.0000x reference)
#include <cuda_runtime.h>
#include <cuda_bf16.h>
#include <cstdint>

// LocallyConnected2d: out[b,o,y,x] = sum_{c,k} x[b,c,y+i,x+j] * w[o,c,y,x,k]
// B=16, C_IN=16, C_OUT=16, H=W=64, OH=OW=62, K=3x3.
//
// R10 = R9 compute structure with xl as the SLOW thread index (warp = 4 xl x
// 8 groups) so x LDS.128s are 8-unique-quad broadcasts (1 wavefront instead
// of 4) and w scalar loads stay 16-bank conflict-free via per-o-group pad.
// Halves compute smem wavefronts at identical instruction count.

#define B_  16
#define CIN 16
#define CO  16
#define H_  64
#define W_  64
#define OH_ 62
#define OW_ 62
#define TX  16
#define NT  128

#define NC  4                        // channels per block (4-way c split)
#define WROWB 148                    // base w row stride (floats)
#define WBUF 2400                    // 16*148 + pad(<=24) rounded up
#define BQS  248                     // x b-quad stride (floats)
#define XBUF (4 * BQS)               // 992 floats

#define WOSTRIDE (CIN * OH_ * OW_ * 9)
#define WCSTRIDE (OH_ * OW_ * 9)
#define XCSTRIDE (H_ * W_)

__device__ __forceinline__ void ffma2(unsigned long long& d,
                                      unsigned long long a,
                                      unsigned long long b) {
    asm("fma.rn.f32x2 %0, %1, %2, %0;" : "+l"(d) : "l"(a), "l"(b));
}

__device__ __forceinline__ unsigned long long bcast2(float v) {
    unsigned long long p;
    asm("mov.b64 %0, {%1, %1};" : "=l"(p) : "f"(v));
    return p;
}

__device__ __forceinline__ void cp_async16(uint32_t dst, const float* src) {
    asm volatile("cp.async.cg.shared.global [%0], [%1], 16;\n"
                 :: "r"(dst), "l"(src));
}

__device__ __forceinline__ void cp_async4(uint32_t dst, const float* src, int sz) {
    asm volatile("cp.async.ca.shared.global [%0], [%1], 4, %2;\n"
                 :: "r"(dst), "l"(src), "r"(sz));
}

__global__ __launch_bounds__(NT, 5)
void lc2d_kernel(const float* __restrict__ xin,
                 const float* __restrict__ wgt,
                 float* __restrict__ out) {
    __shared__ __align__(16) float sh_w[3 * WBUF];
    __shared__ __align__(16) float sh_x[3 * XBUF];

    const int tid = threadIdx.x;
    const int grp = tid & 7;       // FAST: 8 groups
    const int xl  = tid >> 3;      // SLOW: 16 x positions
    const int bh  = grp & 1;       // b half
    const int ob  = grp >> 1;      // o group

    const int y  = blockIdx.y;
    const int x0 = blockIdx.x * TX;
    const int xt = min(TX, OW_ - x0);       // 16 or 14
    const int c0 = blockIdx.z * NC;
    const int sh = 2 * (y & 1);             // uniform 16B-alignment shift

    const uint32_t shw_base = (uint32_t)__cvta_generic_to_shared(sh_w);
    const uint32_t shx_base = (uint32_t)__cvta_generic_to_shared(sh_x);

    // ---- weight staging descriptors (16B chunks, 5 slots) ----
    // smem row for o: o*148 + (o>>2)*8  (pad keeps 16B align, breaks bank tie)
    const int rowch  = (xt == TX) ? 37 : 32;
    const int nchunk = CO * rowch;
    const float* wcbase = wgt + (((c0 * OH_ + y) * OW_ + x0) * 9) - sh;

    int      wsoff[5];
    uint32_t wdst[5];
    bool     wok[5];
    #pragma unroll
    for (int n = 0; n < 5; ++n) {
        int m = tid + NT * n;
        wok[n] = (m < nchunk);
        int o   = m / rowch;
        int ci4 = (m - o * rowch) * 4;
        if (o > 15) { o = 15; ci4 = 0; }
        wsoff[n] = o * WOSTRIDE + ci4;
        wdst[n]  = (uint32_t)(o * WROWB + (o >> 2) * 8 + ci4) * 4;
    }

    // ---- x staging descriptors (4B, b-quad interleaved, 7 slots) ----
    int      xsrcoff[7], xsz[7];
    uint32_t xdst[7];
    bool     xvalid[7];
    #pragma unroll
    for (int n = 0; n < 7; ++n) {
        int m = tid + NT * n;
        xvalid[n] = (m < B_ * 54);
        int b   = m / 54;
        int rem = m - b * 54;
        int r   = rem / 18;
        int cc  = rem - r * 18;
        if (!xvalid[n]) { b = 0; r = 0; cc = 0; }
        bool ok = xvalid[n] && (x0 + cc < W_);
        xsrcoff[n] = (b * CIN) * XCSTRIDE + r * W_ + cc;
        xsz[n]     = ok ? 4 : 0;
        xdst[n] = (uint32_t)((b >> 2) * BQS + r * 80 + cc * 4 + (b & 3)) * 4;
    }
    const float* xbase = xin + (c0 * H_ + y) * W_ + x0;

    unsigned long long acc[4][2][2];    // [oo][q][pair]: b=(bh*2+q)*4+2*pair
    #pragma unroll
    for (int oo = 0; oo < 4; ++oo)
        #pragma unroll
        for (int q = 0; q < 2; ++q) { acc[oo][q][0] = 0ull; acc[oo][q][1] = 0ull; }

    auto stage = [&](int buf, int ci) {
        uint32_t wb = shw_base + (uint32_t)buf * (WBUF * 4);
        const float* wc = wcbase + ci * WCSTRIDE;
        #pragma unroll
        for (int n = 0; n < 5; ++n)
            if (wok[n]) cp_async16(wb + wdst[n], wc + wsoff[n]);
        uint32_t xb = shx_base + (uint32_t)buf * (XBUF * 4);
        const float* xc = xbase + ci * XCSTRIDE;
        #pragma unroll
        for (int n = 0; n < 7; ++n)
            if (xvalid[n])
                cp_async4(xb + xdst[n], xc + xsrcoff[n], xsz[n]);
        asm volatile("cp.async.commit_group;\n" ::: "memory");
    };

    stage(0, 0);
    stage(1, 1);

    int rd = 0;
    #pragma unroll 1
    for (int ci = 0; ci < NC; ++ci) {
        if (ci < NC - 1) {
            asm volatile("cp.async.wait_group 1;\n" ::: "memory");
        } else {
            asm volatile("cp.async.wait_group 0;\n" ::: "memory");
        }
        __syncthreads();

        if (ci + 2 < NC) {
            int st = rd - 1; if (st < 0) st += 3;
            stage(st, ci + 2);
        }

        // w row base for this thread's o-group: ob*600 + oo*148 (+xl*9+k+sh)
        const float* swb = sh_w + rd * WBUF + ob * 600 + xl * 9 + sh;
        const float* sxb = sh_x + rd * XBUF + bh * (2 * BQS);

        #pragma unroll
        for (int k = 0; k < 9; ++k) {
            const int i = k / 3;
            const int j = k - i * 3;
            const float* xp = &sxb[i * 80 + (xl + j) * 4];
            ulonglong2 xq0 = *reinterpret_cast<const ulonglong2*>(xp);
            ulonglong2 xq1 = *reinterpret_cast<const ulonglong2*>(xp + BQS);
            #pragma unroll
            for (int oo = 0; oo < 4; ++oo) {
                float wv = swb[oo * WROWB + k];
                unsigned long long wb2 = bcast2(wv);
                ffma2(acc[oo][0][0], xq0.x, wb2);
                ffma2(acc[oo][0][1], xq0.y, wb2);
                ffma2(acc[oo][1][0], xq1.x, wb2);
                ffma2(acc[oo][1][1], xq1.y, wb2);
            }
        }

        ++rd; if (rd == 3) rd = 0;
    }

    // ---- epilogue: scalar atomics (proven), 4 contributions/elem ----
    if (xl < xt) {
        #pragma unroll
        for (int oo = 0; oo < 4; ++oo) {
            const int o = ob * 4 + oo;
            #pragma unroll
            for (int q = 0; q < 2; ++q) {
                const int bq = (bh * 2 + q) * 4;
                #pragma unroll
                for (int p = 0; p < 2; ++p) {
                    float lo, hi;
                    asm("mov.b64 {%0, %1}, %2;"
                        : "=f"(lo), "=f"(hi) : "l"(acc[oo][q][p]));
                    const int b = bq + 2 * p;
                    atomicAdd(&out[((b * CO + o)       * OH_ + y) * OW_ + x0 + xl], lo);
                    atomicAdd(&out[(((b + 1) * CO + o) * OH_ + y) * OW_ + x0 + xl], hi);
                }
            }
        }
    }
}

extern "C" void kernel_launch(void* const* d_in, const int* in_sizes, int n_in,
                              void* d_out, int out_size) {
    const float* x = (const float*)d_in[0];
    const float* w = (const float*)d_in[1];
    float* out = (float*)d_out;

    cudaMemsetAsync(out, 0, (size_t)out_size * sizeof(float));

    dim3 grid((OW_ + TX - 1) / TX, OH_, 4);   // (4, 62, 4) = 992 blocks
    lc2d_kernel<<<grid, NT>>>(x, w, out);
}